// round 12
// baseline (speedup 1.0000x reference)
#include <cuda_runtime.h>
#include <cstdint>

// Problem constants
#define B_   4
#define H_   384
#define W_   1280
#define GH_  192                 // int(0.5 * 384)
#define N_   (GH_ * W_)          // 245760 ground points per batch
#define HW_  (H_ * W_)           // 491520
#define HYP  25                  // MAX_IT
#define NPTS 5
#define TOLF 0.1f

#define NV_A (HW_ / 4)           // 122880 float4 groups per batch (full image)
#define GX   120                 // blocks per batch: 120*256*4 f4 = NV_A exact
#define FPT  4                   // float4 per thread
#define GB0  60                  // ground starts at f4 61440 = block 60 exactly
#define NGB  (GX - GB0)          // 60 ground blocks per batch

// Scratch (no cudaMalloc; zero-initialized, self-resetting each run)
__device__ float        g_ws[B_ * HYP * 3];
__device__ int          g_cnt[B_ * HYP];
__device__ unsigned int g_done[B_];
__device__ unsigned int g_wsflag[B_];
__device__ unsigned int g_bestflag[B_];
__device__ unsigned int g_ack[B_];
__device__ float        g_best[B_ * 3];

// ---------------------------------------------------------------------------
// ONE kernel, one co-resident wave (480 blocks <= 4/SM * 148 guaranteed by
// __launch_bounds__(256,4) => regs<=64). Data loaded ONCE and reused for
// count and dist. In-kernel flag barriers replace kernel launches.
// ---------------------------------------------------------------------------
__global__ void __launch_bounds__(256, 4) k_all(const float* __restrict__ pts,
                                                const int* __restrict__ rind,
                                                float* __restrict__ out,
                                                float* __restrict__ out_bw) {
    const int b   = blockIdx.y;
    const int bx  = blockIdx.x;
    const int tid = threadIdx.x;

    const float*  base = pts + (size_t)b * 3 * HW_;
    const float4* xs = (const float4*)base;
    const float4* ys = xs + NV_A;
    const float4* zs = xs + 2 * NV_A;
    float4* o = (float4*)(out + (size_t)b * HW_);

    __shared__ float s_y[FPT * 4 * 256];    // y components, [comp*256+tid]
    __shared__ float sx[HYP * NPTS], sy[HYP * NPTS], sz[HYP * NPTS];
    __shared__ float s_w[HYP * 3];
    __shared__ int   s_c[HYP];

    // ---- Phase 0: issue this block's 12 LDG.128 (x,z stay in regs; y->smem)
    const int v0 = bx * (256 * FPT) + tid;
    float4 X[FPT], Z[FPT];
#pragma unroll
    for (int i = 0; i < FPT; i++) {
        X[i] = xs[v0 + i * 256];
        Z[i] = zs[v0 + i * 256];
        float4 y = ys[v0 + i * 256];
        s_y[(4 * i + 0) * 256 + tid] = y.x;
        s_y[(4 * i + 1) * 256 + tid] = y.y;
        s_y[(4 * i + 2) * 256 + tid] = y.z;
        s_y[(4 * i + 3) * 256 + tid] = y.w;
    }

    // ---- Phase 1: block (0,b) gathers samples + solves 25 LS systems (fp64)
    if (bx == 0) {
        if (tid < HYP * NPTS) {
            int n = __ldg(rind + b * (HYP * NPTS) + tid);
            const float* gb = base + (size_t)(H_ - GH_) * W_;
            sx[tid] = __ldg(gb + n);
            sy[tid] = __ldg(gb + HW_ + n);
            sz[tid] = __ldg(gb + 2 * HW_ + n);
        }
        __syncthreads();
        if (tid < HYP) {
            int oo = tid * NPTS;
            double x0 = sx[oo], x1 = sx[oo+1], x2 = sx[oo+2], x3 = sx[oo+3], x4 = sx[oo+4];
            double y0 = sy[oo], y1 = sy[oo+1], y2 = sy[oo+2], y3 = sy[oo+3], y4 = sy[oo+4];
            double z0 = sz[oo], z1 = sz[oo+1], z2 = sz[oo+2], z3 = sz[oo+3], z4 = sz[oo+4];

            #define PW(e0,e1,e2,e3,e4) (((e0)+(e1)) + (((e2)+(e3)) + (e4)))
            double Sxx = PW(x0*x0, x1*x1, x2*x2, x3*x3, x4*x4);
            double Sxz = PW(x0*z0, x1*z1, x2*z2, x3*z3, x4*z4);
            double Sx  = PW(x0, x1, x2, x3, x4);
            double Szz = PW(z0*z0, z1*z1, z2*z2, z3*z3, z4*z4);
            double Sz  = PW(z0, z1, z2, z3, z4);
            double Sxy = PW(x0*y0, x1*y1, x2*y2, x3*y3, x4*y4);
            double Szy = PW(z0*y0, z1*y1, z2*y2, z3*y3, z4*y4);
            double Sy  = PW(y0, y1, y2, y3, y4);
            #undef PW

            // M = A^T A + 1e-6 on EVERY entry (matches jnp broadcast)
            const double e = 1e-6;
            double a  = Sxx + e, bb = Sxz + e, c = Sx + e;
            double d  = Szz + e, f  = Sz  + e;
            double g  = (double)NPTS + e;

            double A00 = d * g - f * f;
            double A01 = c * f - bb * g;
            double A02 = bb * f - c * d;
            double A11 = a * g - c * c;
            double A12 = bb * c - a * f;
            double A22 = a * d - bb * bb;
            double det = (a * A00 + bb * A01) + c * A02;

            // fp32-seeded Newton reciprocal (~2^-46 rel err; outputs fp32)
            double inv = (double)__frcp_rn((float)det);
            inv = inv * (2.0 - det * inv);
            inv = inv * (2.0 - det * inv);

            double r0 = Sxy, r1 = Szy, r2 = Sy;
            g_ws[(b * HYP + tid) * 3 + 0] = (float)(((A00 * r0 + A01 * r1) + A02 * r2) * inv);
            g_ws[(b * HYP + tid) * 3 + 1] = (float)(((A01 * r0 + A11 * r1) + A12 * r2) * inv);
            g_ws[(b * HYP + tid) * 3 + 2] = (float)(((A02 * r0 + A12 * r1) + A22 * r2) * inv);
        }
        __syncthreads();
        if (tid == 0) {
            __threadfence();
            atomicExch(&g_wsflag[b], 1u);       // release
        }
    }

    // ---- Phase 2: ground blocks count inliers
    if (bx >= GB0) {
        if (tid == 0) {
            while (((volatile unsigned int*)g_wsflag)[b] == 0u) __nanosleep(32);
            __threadfence();                     // acquire
        }
        __syncthreads();
        if (tid < HYP * 3) s_w[tid] = __ldcg(&g_ws[b * HYP * 3 + tid]);
        if (tid < HYP)     s_c[tid] = 0;
        __syncthreads();

        for (int k = 0; k < HYP; k++) {
            float w0 = s_w[3 * k], w1 = s_w[3 * k + 1], w2 = s_w[3 * k + 2];
            int c = 0;
#pragma unroll
            for (int i = 0; i < FPT; i++) {
                c += (fabsf(fmaf(X[i].x, w0, fmaf(Z[i].x, w1, w2)) - s_y[(4*i+0)*256 + tid]) < TOLF);
                c += (fabsf(fmaf(X[i].y, w0, fmaf(Z[i].y, w1, w2)) - s_y[(4*i+1)*256 + tid]) < TOLF);
                c += (fabsf(fmaf(X[i].z, w0, fmaf(Z[i].z, w1, w2)) - s_y[(4*i+2)*256 + tid]) < TOLF);
                c += (fabsf(fmaf(X[i].w, w0, fmaf(Z[i].w, w1, w2)) - s_y[(4*i+3)*256 + tid]) < TOLF);
            }
            unsigned s = __reduce_add_sync(0xffffffffu, (unsigned)c);
            if ((tid & 31) == 0) atomicAdd(&s_c[k], (int)s);
        }
        __syncthreads();
        if (tid < HYP) atomicAdd(&g_cnt[b * HYP + tid], s_c[tid]);

        // ---- Phase 3: ticket — last ground block does argmax + reset
        if (tid == 0) {
            __threadfence();
            unsigned old = atomicAdd(&g_done[b], 1u);
            if (old == NGB - 1) {
                int best = 0, bc = __ldcg(&g_cnt[b * HYP]);
#pragma unroll
                for (int it = 1; it < HYP; it++) {
                    int v = __ldcg(&g_cnt[b * HYP + it]);
                    if (v > bc) { bc = v; best = it; }    // first-max = jnp.argmax
                }
                float bw0 = s_w[best * 3 + 0];
                float bw1 = s_w[best * 3 + 1];
                float bw2 = s_w[best * 3 + 2];
                g_best[b * 3 + 0] = bw0;
                g_best[b * 3 + 1] = bw1;
                g_best[b * 3 + 2] = bw2;
                out_bw[b * 3 + 0] = bw0;
                out_bw[b * 3 + 1] = bw1;
                out_bw[b * 3 + 2] = bw2;
                // reset count state for the next graph replay
#pragma unroll
                for (int it = 0; it < HYP; it++) g_cnt[b * HYP + it] = 0;
                g_done[b]   = 0;
                g_wsflag[b] = 0;
                __threadfence();
                atomicExch(&g_bestflag[b], 1u);  // release
            }
        }
    }

    // ---- Phase 4: all blocks wait for best_w, then dist from resident regs
    if (tid == 0) {
        while (((volatile unsigned int*)g_bestflag)[b] == 0u) __nanosleep(32);
        __threadfence();                         // acquire
    }
    __syncthreads();

    float w0 = __ldcg(&g_best[b * 3 + 0]);
    float w1 = __ldcg(&g_best[b * 3 + 1]);
    float w2 = __ldcg(&g_best[b * 3 + 2]);

#pragma unroll
    for (int i = 0; i < FPT; i++) {
        float4 r;
        r.x = fmaf(X[i].x, w0, fmaf(Z[i].x, w1, w2)) - s_y[(4*i+0)*256 + tid];
        r.y = fmaf(X[i].y, w0, fmaf(Z[i].y, w1, w2)) - s_y[(4*i+1)*256 + tid];
        r.z = fmaf(X[i].z, w0, fmaf(Z[i].z, w1, w2)) - s_y[(4*i+2)*256 + tid];
        r.w = fmaf(X[i].w, w0, fmaf(Z[i].w, w1, w2)) - s_y[(4*i+3)*256 + tid];
        o[v0 + i * 256] = r;
    }

    // ---- Phase 5: ack; last block resets the best flag for the next replay
    __syncthreads();
    if (tid == 0) {
        unsigned a = atomicAdd(&g_ack[b], 1u);
        if (a == GX - 1) {
            g_ack[b] = 0;
            __threadfence();
            atomicExch(&g_bestflag[b], 0u);
        }
    }
}

// ---------------------------------------------------------------------------
// Launch: ONE kernel, graph-capturable (no syncs, no allocs).
// Output layout: dist (B*H*W floats) followed by best_w (B*3 floats).
// ---------------------------------------------------------------------------
extern "C" void kernel_launch(void* const* d_in, const int* in_sizes, int n_in,
                              void* d_out, int out_size) {
    const float* pts  = (const float*)d_in[0];
    const int*   rind = (const int*)d_in[1];
    float*       out  = (float*)d_out;

    k_all<<<dim3(GX, B_), 256>>>(pts, rind, out, out + (size_t)B_ * HW_);
}